// round 1
// baseline (speedup 1.0000x reference)
#include <cuda_runtime.h>
#include <cuda_bf16.h>
#include <math.h>

// ---------------- constants ----------------
#define BB 4
#define TT 20
#define ST 64          // S_TEXT
#define SA 32          // S_AUDIO
#define DD 256
#define DS 64          // D_STATE
#define VOCAB 32000
#define AF 128
#define HEADS 8
#define HD 32
#define LQ 1280        // T*S_TEXT
#define LKV 1920       // T*(S_TEXT+S_AUDIO)
#define KTOP 19660     // int(65536*0.3)
#define NFLAT 65536    // B*S_TEXT*D

// ---------------- scratch (device globals; no allocs allowed) ----------------
__device__ float g_xtext [BB*ST*DD];
__device__ float g_xaudio[BB*SA*DD];
__device__ float g_hidden[BB*SA*(DD/2)];
__device__ float g_Q  [BB*LQ*DD];
__device__ float g_K  [BB*LKV*DD];
__device__ float g_V  [BB*LKV*DD];
__device__ float g_att[BB*LQ*DD];
__device__ float g_bufA[BB*LQ*DD];
__device__ float g_bufB[BB*LQ*DD];
__device__ float g_U  [BB*TT*ST*DS];
__device__ float g_H  [BB*TT*ST*DS];
__device__ float g_feat[BB*ST*DD];
__device__ unsigned g_theta[TT];
__device__ int      g_Rk[TT];
__device__ int      g_keepf[TT];

// ---------------- helpers ----------------
__device__ __forceinline__ int ttfs_t(float x) {
    float u  = 1.0f / (1.0f + expf(-x));       // sigmoid
    float tf = floorf((1.0f - u) * 19.0f);     // (T-1)=19
    int   t  = (int)tf;
    return min(max(t, 0), 19);
}

// ---------------- text embedding gather ----------------
__global__ void gather_text_kernel(const float* __restrict__ emb,
                                   const int* __restrict__ ids,
                                   float* __restrict__ x) {
    int row = blockIdx.x;           // b*64+s, 256 rows
    int d   = threadIdx.x;          // 256
    x[row*DD + d] = emb[(long long)ids[row]*DD + d];
}

// ---------------- generic tiled GEMM: C = A[MxK] * B[KxN] (+bias)(relu) ----------
// block tile 64x64, threads 256 (16x16), thread tile 4x4, K chunk 16.
// Requires M%64==0, N%64==0, K%16==0 (true for all uses here).
__global__ __launch_bounds__(256) void gemm64_kernel(
    const float* __restrict__ A, const float* __restrict__ B,
    const float* __restrict__ bias, float* __restrict__ C,
    int M, int N, int K, int relu)
{
    __shared__ float As[64][17];
    __shared__ float Bs[16][64];
    int tx = threadIdx.x & 15, ty = threadIdx.x >> 4;
    int row0 = blockIdx.y * 64, col0 = blockIdx.x * 64;
    float acc[4][4];
#pragma unroll
    for (int i = 0; i < 4; i++)
#pragma unroll
        for (int j = 0; j < 4; j++) acc[i][j] = 0.f;

    for (int k0 = 0; k0 < K; k0 += 16) {
        for (int i = threadIdx.x; i < 1024; i += 256) {
            int r = i >> 4, kk = i & 15;
            As[r][kk] = A[(long long)(row0 + r) * K + k0 + kk];
        }
        for (int i = threadIdx.x; i < 1024; i += 256) {
            int kk = i >> 6, c = i & 63;
            Bs[kk][c] = B[(long long)(k0 + kk) * N + col0 + c];
        }
        __syncthreads();
#pragma unroll
        for (int kk = 0; kk < 16; kk++) {
            float4 bv = *reinterpret_cast<const float4*>(&Bs[kk][tx * 4]);
            float a0 = As[ty*4+0][kk], a1 = As[ty*4+1][kk];
            float a2 = As[ty*4+2][kk], a3 = As[ty*4+3][kk];
            acc[0][0] += a0*bv.x; acc[0][1] += a0*bv.y; acc[0][2] += a0*bv.z; acc[0][3] += a0*bv.w;
            acc[1][0] += a1*bv.x; acc[1][1] += a1*bv.y; acc[1][2] += a1*bv.z; acc[1][3] += a1*bv.w;
            acc[2][0] += a2*bv.x; acc[2][1] += a2*bv.y; acc[2][2] += a2*bv.z; acc[2][3] += a2*bv.w;
            acc[3][0] += a3*bv.x; acc[3][1] += a3*bv.y; acc[3][2] += a3*bv.z; acc[3][3] += a3*bv.w;
        }
        __syncthreads();
    }
    int c0 = col0 + tx * 4;
    float4 bb = make_float4(0.f, 0.f, 0.f, 0.f);
    if (bias) bb = *reinterpret_cast<const float4*>(&bias[c0]);
#pragma unroll
    for (int i = 0; i < 4; i++) {
        int r = row0 + ty * 4 + i;
        float4 v;
        v.x = acc[i][0] + bb.x; v.y = acc[i][1] + bb.y;
        v.z = acc[i][2] + bb.z; v.w = acc[i][3] + bb.w;
        if (relu) {
            v.x = fmaxf(v.x, 0.f); v.y = fmaxf(v.y, 0.f);
            v.z = fmaxf(v.z, 0.f); v.w = fmaxf(v.w, 0.f);
        }
        *reinterpret_cast<float4*>(&C[(long long)r * N + c0]) = v;
    }
}

// ---------------- QKV projection exploiting TTFS one-hot sparsity ----------------
// For a fixed (b, source-row s) the 20 time-rows of `combined` partition the 256
// dims by their firing step. One dense 256x256 matvec covers all 20 output rows.
__global__ __launch_bounds__(256) void qkv_kernel(
    const float* __restrict__ xtext, const float* __restrict__ xaudio,
    const float* __restrict__ wq, const float* __restrict__ bq,
    const float* __restrict__ wk, const float* __restrict__ bk,
    const float* __restrict__ wv, const float* __restrict__ bv,
    float* __restrict__ Q, float* __restrict__ K, float* __restrict__ V)
{
    int sidx = blockIdx.x;      // 0..95 (0..63 text, 64..95 audio)
    int mat  = blockIdx.y;      // 0=Q 1=K 2=V
    int b    = blockIdx.z;
    bool is_text = sidx < 64;
    if (mat == 0 && !is_text) return;   // Q only needed for text rows

    __shared__ float xs[256];
    __shared__ int   ttx[256];
    __shared__ int   cnt[21];
    __shared__ int   order[256];
    int tid = threadIdx.x;
    if (tid < 21) cnt[tid] = 0;
    __syncthreads();

    const float* src = is_text ? (xtext + (b*ST + sidx)*DD)
                               : (xaudio + (b*SA + (sidx-64))*DD);
    float x = src[tid];
    int g = ttfs_t(x);
    xs[tid] = x; ttx[tid] = g;
    atomicAdd(&cnt[g + 1], 1);
    __syncthreads();
    if (tid == 0) {
        for (int i = 1; i < 21; i++) cnt[i] += cnt[i-1];
        int cur[20];
        for (int i = 0; i < 20; i++) cur[i] = cnt[i];
        for (int d = 0; d < 256; d++) order[cur[ttx[d]]++] = d;  // stable by index
    }
    __syncthreads();

    const float* W; const float* bi; float* out;
    if (mat == 0)      { W = wq; bi = bq; out = Q; }
    else if (mat == 1) { W = wk; bi = bk; out = K; }
    else               { W = wv; bi = bv; out = V; }
    float bias_c = bi[tid];

    for (int gg = 0; gg < 20; gg++) {
        float acc = bias_c;
        int e = cnt[gg + 1];
        for (int i = cnt[gg]; i < e; i++) {
            int d = order[i];
            acc += xs[d] * W[d * DD + tid];
        }
        int row;
        if (mat == 0) row = b*LQ + gg*ST + sidx;
        else row = b*LKV + (is_text ? (gg*ST + sidx) : (LQ + gg*SA + (sidx-64)));
        out[(long long)row * DD + tid] = acc;
    }
}

// ---------------- flash-style attention, fp32 ----------------
__global__ __launch_bounds__(128, 2) void attn_kernel(
    const float* __restrict__ Qg, const float* __restrict__ Kg,
    const float* __restrict__ Vg, float* __restrict__ Og)
{
    int qt = blockIdx.x, h = blockIdx.y, b = blockIdx.z;
    int tid = threadIdx.x;
    int row = qt * 128 + tid;   // 0..1279

    const float scale = 0.17677669529663689f;   // 1/sqrt(32)
    float q[HD], acc[HD];
    const float* qp = Qg + ((long long)(b*LQ + row))*DD + h*HD;
#pragma unroll
    for (int d = 0; d < HD; d++) { q[d] = qp[d]; acc[d] = 0.f; }
    float m = -1e30f, lsum = 0.f;

    __shared__ float Ks[32*HD];
    __shared__ float Vs[32*HD];

    for (int kv0 = 0; kv0 < LKV; kv0 += 32) {
        __syncthreads();
        for (int i = tid; i < 32*HD; i += 128) {
            int j = i >> 5, d = i & 31;
            long long gidx = ((long long)(b*LKV + kv0 + j))*DD + h*HD + d;
            Ks[i] = Kg[gidx];
            Vs[i] = Vg[gidx];
        }
        __syncthreads();
        float s[32];
#pragma unroll
        for (int j = 0; j < 32; j++) {
            float a = 0.f;
#pragma unroll
            for (int d = 0; d < HD; d++) a += q[d] * Ks[j*HD + d];
            s[j] = a * scale;
        }
        float mt = m;
#pragma unroll
        for (int j = 0; j < 32; j++) mt = fmaxf(mt, s[j]);
        float corr = __expf(m - mt);
        m = mt; lsum *= corr;
#pragma unroll
        for (int d = 0; d < HD; d++) acc[d] *= corr;
#pragma unroll
        for (int j = 0; j < 32; j++) {
            float p = __expf(s[j] - mt);
            lsum += p;
#pragma unroll
            for (int d = 0; d < HD; d++) acc[d] += p * Vs[j*HD + d];
        }
    }
    float inv = 1.0f / lsum;
    float* op = Og + ((long long)(b*LQ + row))*DD + h*HD;
#pragma unroll
    for (int d = 0; d < HD; d++) op[d] = acc[d] * inv;
}

// ---------------- temporal diff thresholding (in place) ----------------
__global__ void diff_kernel(float* __restrict__ buf) {
    int idx = blockIdx.x * 256 + threadIdx.x;   // 65536 = (b, s*256+d)
    int b = idx >> 14, rem = idx & 16383;
    float* p = buf + (long long)b * (LQ*DD) + rem;   // t stride = 16384
    float prev = p[0];
    for (int t = 1; t < TT; t++) {
        float cur = p[t * 16384];
        float out = (fabsf(cur - prev) > 0.1f) ? cur : 0.f;
        p[t * 16384] = out;
        prev = out;
    }
}

// ---------------- exact k-th largest |v| per timestep via radix select ----------
__global__ __launch_bounds__(256) void select_kernel(const float* __restrict__ buf) {
    int t = blockIdx.x, tid = threadIdx.x;
    __shared__ unsigned hist[256];
    __shared__ float ssum[256];
    __shared__ unsigned sh_prefix;
    __shared__ int sh_need;
    __shared__ int cgt;

    // signed sum for the keep guard
    float s = 0.f;
    for (int f = tid; f < NFLAT; f += 256) {
        int b = f >> 14, rem = f & 16383;
        s += buf[(long long)b*(LQ*DD) + t*16384 + rem];
    }
    ssum[tid] = s; __syncthreads();
    for (int off = 128; off > 0; off >>= 1) {
        if (tid < off) ssum[tid] += ssum[tid + off];
        __syncthreads();
    }
    if (tid == 0) g_keepf[t] = (ssum[0] > 0.f) ? 1 : 0;

    unsigned prefix = 0;
    for (int p = 3; p >= 0; p--) {
        hist[tid] = 0; __syncthreads();
        unsigned himask = (p == 3) ? 0u : (0xFFFFFFFFu << ((p + 1) * 8));
        for (int f = tid; f < NFLAT; f += 256) {
            int b = f >> 14, rem = f & 16383;
            unsigned u = __float_as_uint(fabsf(buf[(long long)b*(LQ*DD) + t*16384 + rem]));
            if ((u & himask) == prefix) atomicAdd(&hist[(u >> (p * 8)) & 255], 1u);
        }
        __syncthreads();
        if (tid == 0) {
            int nd = (p == 3) ? KTOP : sh_need;
            int dig = 0;
            for (int d2 = 255; d2 >= 0; d2--) {
                int c = (int)hist[d2];
                if (nd <= c) { dig = d2; break; }
                nd -= c;
            }
            sh_prefix = prefix | ((unsigned)dig << (p * 8));
            sh_need = nd;
        }
        __syncthreads();
        prefix = sh_prefix;
        __syncthreads();
    }
    if (tid == 0) cgt = 0;
    __syncthreads();
    int loc = 0;
    for (int f = tid; f < NFLAT; f += 256) {
        int b = f >> 14, rem = f & 16383;
        unsigned u = __float_as_uint(fabsf(buf[(long long)b*(LQ*DD) + t*16384 + rem]));
        if (u > prefix) loc++;
    }
    atomicAdd(&cgt, loc);
    __syncthreads();
    if (tid == 0) { g_theta[t] = prefix; g_Rk[t] = KTOP - cgt; }
}

// ---------------- apply mask (ties kept in flat-index order, like top_k) --------
__global__ __launch_bounds__(1024) void apply_kernel(float* __restrict__ buf) {
    int t = blockIdx.x, tid = threadIdx.x;
    if (!g_keepf[t]) return;                 // uniform per block
    unsigned theta = g_theta[t];
    int R = g_Rk[t];
    __shared__ int warp_tot[32];
    __shared__ int warp_base[32];
    __shared__ int running_s;
    if (tid == 0) running_s = 0;
    __syncthreads();
    int lane = tid & 31, w = tid >> 5;

    for (int c = 0; c < 64; c++) {
        int f = c * 1024 + tid;
        int b = f >> 14, rem = f & 16383;
        float* p = buf + (long long)b*(LQ*DD) + t*16384 + rem;
        float v = *p;
        unsigned u = __float_as_uint(fabsf(v));
        bool gt  = (u > theta);
        bool tie = (u == theta);
        unsigned bal = __ballot_sync(0xFFFFFFFFu, tie);
        int wpre = __popc(bal & ((1u << lane) - 1u));
        if (lane == 0) warp_tot[w] = __popc(bal);
        __syncthreads();
        if (tid == 0) {
            int run = running_s;
            for (int i = 0; i < 32; i++) { warp_base[i] = run; run += warp_tot[i]; }
            running_s = run;
        }
        __syncthreads();
        int rank = warp_base[w] + wpre;
        bool keepmask = gt || (tie && rank < R);
        *p = keepmask ? v : 0.f;
        __syncthreads();
    }
}

// ---------------- SSM recurrence (U precomputed via GEMM) ----------------
__global__ void ssm_scan_kernel(const float* __restrict__ U,
                                const float* __restrict__ Avec,
                                float* __restrict__ H)
{
    int bs = blockIdx.x;      // 0..255 = b*64+s
    int j  = threadIdx.x;     // 0..63
    int b = bs >> 6, s = bs & 63;
    float a = Avec[j];
    float h = 0.f;
    for (int t = 0; t < TT; t++) {
        int row = (b*TT + t)*ST + s;
        h = h * a + U[(long long)row*DS + j];
        H[(long long)row*DS + j] = h;
    }
}

// ---------------- mean over time ----------------
__global__ void mean_kernel(const float* __restrict__ Y, float* __restrict__ feat) {
    int idx = blockIdx.x * 256 + threadIdx.x;   // 65536
    int b = idx >> 14, rem = idx & 16383;
    float acc = 0.f;
    for (int t = 0; t < TT; t++)
        acc += Y[(long long)b*(LQ*DD) + t*16384 + rem];
    feat[idx] = acc * 0.05f;
}

// ---------------- launch ----------------
extern "C" void kernel_launch(void* const* d_in, const int* in_sizes, int n_in,
                              void* d_out, int out_size)
{
    const int*   text_input = (const int*)  d_in[0];
    const float* audio      = (const float*)d_in[1];
    const float* emb        = (const float*)d_in[2];
    const float* aw1 = (const float*)d_in[3];
    const float* ab1 = (const float*)d_in[4];
    const float* aw2 = (const float*)d_in[5];
    const float* ab2 = (const float*)d_in[6];
    const float* wq  = (const float*)d_in[7];
    const float* bq  = (const float*)d_in[8];
    const float* wk  = (const float*)d_in[9];
    const float* bk  = (const float*)d_in[10];
    const float* wv  = (const float*)d_in[11];
    const float* bv  = (const float*)d_in[12];
    const float* wo  = (const float*)d_in[13];
    const float* bo  = (const float*)d_in[14];
    const float* Am  = (const float*)d_in[15];
    const float* Bm  = (const float*)d_in[16];
    const float* Cm  = (const float*)d_in[17];
    const float* wout = (const float*)d_in[18];
    const float* bout = (const float*)d_in[19];
    float* out = (float*)d_out;

    float *p_xtext, *p_xaudio, *p_hidden, *p_Q, *p_K, *p_V, *p_att;
    float *p_A, *p_B, *p_U, *p_H, *p_feat;
    cudaGetSymbolAddress((void**)&p_xtext,  g_xtext);
    cudaGetSymbolAddress((void**)&p_xaudio, g_xaudio);
    cudaGetSymbolAddress((void**)&p_hidden, g_hidden);
    cudaGetSymbolAddress((void**)&p_Q,   g_Q);
    cudaGetSymbolAddress((void**)&p_K,   g_K);
    cudaGetSymbolAddress((void**)&p_V,   g_V);
    cudaGetSymbolAddress((void**)&p_att, g_att);
    cudaGetSymbolAddress((void**)&p_A,   g_bufA);
    cudaGetSymbolAddress((void**)&p_B,   g_bufB);
    cudaGetSymbolAddress((void**)&p_U,   g_U);
    cudaGetSymbolAddress((void**)&p_H,   g_H);
    cudaGetSymbolAddress((void**)&p_feat, g_feat);

    // 1. text embed + audio MLP
    gather_text_kernel<<<BB*ST, DD>>>(emb, text_input, p_xtext);
    gemm64_kernel<<<dim3(2, 2), 256>>>(audio, aw1, ab1, p_hidden, BB*SA, DD/2, AF, 1);
    gemm64_kernel<<<dim3(4, 2), 256>>>(p_hidden, aw2, ab2, p_xaudio, BB*SA, DD, DD/2, 0);

    // 2. QKV with TTFS-sparsity counting sort
    qkv_kernel<<<dim3(96, 3, BB), 256>>>(p_xtext, p_xaudio,
                                         wq, bq, wk, bk, wv, bv,
                                         p_Q, p_K, p_V);

    // 3. attention + output projection
    attn_kernel<<<dim3(LQ/128, HEADS, BB), 128>>>(p_Q, p_K, p_V, p_att);
    gemm64_kernel<<<dim3(DD/64, (BB*LQ)/64), 256>>>(p_att, wo, bo, p_A, BB*LQ, DD, DD, 0);

    // 4. spike sparsification
    diff_kernel<<<NFLAT/256, 256>>>(p_A);
    select_kernel<<<TT, 256>>>(p_A);
    apply_kernel<<<TT, 1024>>>(p_A);

    // 5. SSM layers (ping-pong A<->B)
    float* cur = p_A;
    float* nxt = p_B;
    for (int i = 0; i < 3; i++) {
        gemm64_kernel<<<dim3(DS/64, (BB*LQ)/64), 256>>>(cur, Bm + i*DD*DS, nullptr,
                                                        p_U, BB*LQ, DS, DD, 0);
        ssm_scan_kernel<<<BB*ST, DS>>>(p_U, Am + i*DS, p_H);
        gemm64_kernel<<<dim3(DD/64, (BB*LQ)/64), 256>>>(p_H, Cm + i*DS*DD, nullptr,
                                                        nxt, BB*LQ, DD, DS, 0);
        float* tmp = cur; cur = nxt; nxt = tmp;
    }
    // after 3 layers, result in `cur`

    // 6. time mean + vocab head
    mean_kernel<<<NFLAT/256, 256>>>(cur, p_feat);
    gemm64_kernel<<<dim3(VOCAB/64, (BB*ST)/64), 256>>>(p_feat, wout, bout, out,
                                                       BB*ST, VOCAB, DD, 0);
}